// round 7
// baseline (speedup 1.0000x reference)
#include <cuda_runtime.h>
#include <cstdint>
#include <math.h>

typedef unsigned long long ull;

static constexpr int kT = 512;
static constexpr int kB = 64;
static constexpr int kH = 500;

// ---------------- static device scratch (allocation-free) ----------------
__device__ float g_Wt[4][4][512][512];                  // W_hh^T: [dirIdx][gate][k][u], zero-padded
__device__ float g_h[2][2][kB][512];                    // [parity][dir][b][u]
__device__ float g_gx0[(size_t)kB * kT * 2000];         // fwd input gates
__device__ float g_gx1[(size_t)kB * kT * 2000];         // bwd input gates
__device__ float g_out0[(size_t)kB * kT * 1000];        // layer-0 output
__device__ int   g_len[kB];
__device__ unsigned g_barcnt;                           // zero-init
__device__ volatile unsigned g_bargen;                  // zero-init

// ---------------- f32x2 helpers -------------------------------------------
__device__ __forceinline__ ull pk2(float lo, float hi) {
    ull r; asm("mov.b64 %0,{%1,%2};" : "=l"(r) : "f"(lo), "f"(hi)); return r;
}
__device__ __forceinline__ void fma2(ull& d, ull a, ull b) {
    asm("fma.rn.f32x2 %0,%1,%2,%0;" : "+l"(d) : "l"(a), "l"(b));
}
__device__ __forceinline__ ull add2(ull a, ull b) {
    ull r; asm("add.rn.f32x2 %0,%1,%2;" : "=l"(r) : "l"(a), "l"(b)); return r;
}
__device__ __forceinline__ float2 upk2(ull v) {
    float2 f; asm("mov.b64 {%0,%1},%2;" : "=f"(f.x), "=f"(f.y) : "l"(v)); return f;
}

// ---------------- lengths: int32 vs int64 detection ------------------------
__global__ void k_len(const void* __restrict__ lenraw) {
    const int* p32 = (const int*)lenraw;
    int i = threadIdx.x;
    // int64 LE: p32[1] = high word of lengths[0] = 0 (len in [1,512]); int32: p32[1] >= 1.
    int v = (p32[1] == 0) ? (int)((const long long*)lenraw)[i] : p32[i];
    if (i < kB) g_len[i] = v;
}

// ---------------- zero h (both parities, both dirs) ------------------------
__global__ void k_zero() {
    int i = blockIdx.x * 256 + threadIdx.x;              // 512*256 = 131072 = 2*2*64*512
    (&g_h[0][0][0][0])[i] = 0.f;
}

// ---------------- pack W_hh [2000][500] -> transposed [4][512 k][512 u] ----
__global__ void k_packW(const float* __restrict__ w0f, const float* __restrict__ w0b,
                        const float* __restrict__ w1f, const float* __restrict__ w1b) {
    size_t i = (size_t)blockIdx.x * 256 + threadIdx.x;   // 4*4*512*512 = 4194304
    int u = (int)(i & 511);
    int k = (int)((i >> 9) & 511);
    int g = (int)((i >> 18) & 3);
    int d = (int)(i >> 20);
    float v = 0.f;
    if (u < kH && k < kH) {
        const float* w = (d == 0) ? w0f : (d == 1) ? w0b : (d == 2) ? w1f : w1b;
        v = w[(size_t)(g * kH + u) * kH + k];
    }
    (&g_Wt[0][0][0][0])[i] = v;
}

// ---------------- input GEMM (f32x2): C[M,2000] = A[M,K] @ W[2000,K]^T + b --
__global__ void __launch_bounds__(256) k_gemm(
    const float* __restrict__ Aext, int useOut0,
    const float* __restrict__ W, const float* __restrict__ bias,
    int dstSel, int K)
{
    const float* __restrict__ A = useOut0 ? g_out0 : Aext;
    float* __restrict__ C = dstSel ? g_gx1 : g_gx0;

    __shared__ __align__(16) ull   AsD[8][128];  // dup-packed A, 8 KB
    __shared__ __align__(16) float Ws[8][128];   // 4 KB

    const int tid = threadIdx.x;
    const int m0 = blockIdx.x * 128;
    const int n0 = blockIdx.y * 128;
    const int lrow = tid >> 1;
    const int lk = (tid & 1) * 4;

    const float* aptr = A + (size_t)(m0 + lrow) * K + lk;
    const int wrow = n0 + lrow;
    const float* wptr = W + (size_t)wrow * K + lk;
    const bool wok = (wrow < 2000);

    ull acc[8][4];
#pragma unroll
    for (int i = 0; i < 8; i++)
#pragma unroll
        for (int j = 0; j < 4; j++) acc[i][j] = 0ULL;

    const int tx = tid & 15, ty = tid >> 4;

    for (int kc = 0; kc < K; kc += 8) {
        float4 av = *(const float4*)aptr; aptr += 8;
        float4 wv = wok ? *(const float4*)wptr : make_float4(0.f, 0.f, 0.f, 0.f);
        wptr += 8;
        __syncthreads();
        AsD[lk + 0][lrow] = pk2(av.x, av.x);
        AsD[lk + 1][lrow] = pk2(av.y, av.y);
        AsD[lk + 2][lrow] = pk2(av.z, av.z);
        AsD[lk + 3][lrow] = pk2(av.w, av.w);
        Ws[lk + 0][lrow] = wv.x; Ws[lk + 1][lrow] = wv.y;
        Ws[lk + 2][lrow] = wv.z; Ws[lk + 3][lrow] = wv.w;
        __syncthreads();
#pragma unroll
        for (int kk = 0; kk < 8; kk++) {
            ull a[8], w[4];
            const ull* ap = &AsD[kk][ty * 8];
#pragma unroll
            for (int i = 0; i < 8; i++) a[i] = ap[i];
            const ull* wp = (const ull*)&Ws[kk][tx * 8];
#pragma unroll
            for (int j = 0; j < 4; j++) w[j] = wp[j];
#pragma unroll
            for (int i = 0; i < 8; i++)
#pragma unroll
                for (int j = 0; j < 4; j++) fma2(acc[i][j], a[i], w[j]);
        }
    }
#pragma unroll
    for (int j = 0; j < 4; j++) {
        int n = n0 + tx * 8 + 2 * j;
        if (n >= 2000) continue;
        float b0 = bias[n];
        float b1 = (n + 1 < 2000) ? bias[n + 1] : 0.f;
#pragma unroll
        for (int i = 0; i < 8; i++) {
            int m = m0 + ty * 8 + i;
            float2 v = upk2(acc[i][j]);
            C[(size_t)m * 2000 + n] = v.x + b0;
            if (n + 1 < 2000) C[(size_t)m * 2000 + n + 1] = v.y + b1;
        }
    }
}

// ---------------- software grid barrier (128 CTAs, all co-resident) --------
__device__ __forceinline__ void grid_bar() {
    __syncthreads();
    if (threadIdx.x == 0) {
        unsigned my = g_bargen;
        __threadfence();
        unsigned old = atomicAdd(&g_barcnt, 1u);
        if (old == 127u) {
            g_barcnt = 0u;
            __threadfence();
            g_bargen = my + 1u;
        } else {
            while (g_bargen == my) { }
            __threadfence();
        }
    }
    __syncthreads();
}

// ---------------- persistent recurrence: all 512 steps, both dirs ----------
__global__ void __launch_bounds__(256) k_rnn(int layer, float* __restrict__ outExt)
{
    __shared__ float h_sm[16][520];   // padded rows: bank-conflict-free, 33.3 KB
    __shared__ ull   sred[128][9];    // 9.2 KB

    const int bid = blockIdx.x;       // 128 CTAs
    const int dir = bid >> 6;         // 0..1
    const int ub  = (bid >> 2) & 15;  // 16 u-blocks of 32 units
    const int bb  = bid & 3;          // 4 b-blocks of 16 batches
    const int tid = threadIdx.x;
    const int kh  = tid >> 7;         // k-half 0/1 (256 k each)
    const int r   = tid & 127;
    const int ug  = r & 7;            // 8 unit-groups of 4 units
    const int bloc = r >> 3;          // 16 batches
    const int b   = bb * 16 + bloc;
    const int u0t = ub * 32 + ug * 4;
    const int dirIdx = layer * 2 + dir;

    const float* __restrict__ gx = dir ? g_gx1 : g_gx0;
    float* __restrict__ outp = layer ? outExt : g_out0;
    const int len = g_len[b];
    const float* __restrict__ wbase = &g_Wt[dirIdx][0][0][u0t];
    const size_t GOFF = (size_t)512 * 512;    // gate stride in floats

    float c0 = 0.f, c1 = 0.f, c2 = 0.f, c3 = 0.f;   // cell state lives in regs
    const int k0 = kh * 256, k1 = k0 + 256;

    for (int s = 0; s < kT; s++) {
        const int parity = s & 1;
        const int t = dir ? (kT - 1 - s) : s;

        // stage h_prev tile [16 b][512] into SMEM (L2-coherent loads)
        {
            const float4* src = (const float4*)&g_h[parity][dir][bb * 16][0];
            for (int i = tid; i < 16 * 128; i += 256) {
                float4 v = __ldcg(src + i);
                *(float4*)&h_sm[i >> 7][(i & 127) * 4] = v;
            }
        }
        __syncthreads();

        ull a00, a01, a10, a11, a20, a21, a30, a31;
        if (kh == 0) {
            const float* gxr = gx + ((size_t)b * kT + t) * 2000;
            float v[4][4];
#pragma unroll
            for (int g = 0; g < 4; g++)
#pragma unroll
                for (int q = 0; q < 4; q++) {
                    int uu = u0t + q;
                    v[g][q] = (uu < kH) ? gxr[g * kH + uu] : 0.f;
                }
            a00 = pk2(v[0][0], v[0][1]); a01 = pk2(v[0][2], v[0][3]);
            a10 = pk2(v[1][0], v[1][1]); a11 = pk2(v[1][2], v[1][3]);
            a20 = pk2(v[2][0], v[2][1]); a21 = pk2(v[2][2], v[2][3]);
            a30 = pk2(v[3][0], v[3][1]); a31 = pk2(v[3][2], v[3][3]);
        } else {
            a00 = a01 = a10 = a11 = a20 = a21 = a30 = a31 = 0ULL;
        }

        const float* __restrict__ hp = &h_sm[bloc][0];
#pragma unroll 4
        for (int k = k0; k < k1; k++) {
            float hv = hp[k];
            ull hd = pk2(hv, hv);
            const float* wk = wbase + (size_t)k * 512;
            ulonglong2 w0 = *(const ulonglong2*)(wk);
            ulonglong2 w1 = *(const ulonglong2*)(wk + GOFF);
            ulonglong2 w2 = *(const ulonglong2*)(wk + 2 * GOFF);
            ulonglong2 w3 = *(const ulonglong2*)(wk + 3 * GOFF);
            fma2(a00, w0.x, hd); fma2(a01, w0.y, hd);
            fma2(a10, w1.x, hd); fma2(a11, w1.y, hd);
            fma2(a20, w2.x, hd); fma2(a21, w2.y, hd);
            fma2(a30, w3.x, hd); fma2(a31, w3.y, hd);
        }

        if (kh == 1) {
            ull* sp = sred[r];
            sp[0] = a00; sp[1] = a01; sp[2] = a10; sp[3] = a11;
            sp[4] = a20; sp[5] = a21; sp[6] = a30; sp[7] = a31;
        }
        __syncthreads();
        if (kh == 0) {
            const ull* sp = sred[r];
            a00 = add2(a00, sp[0]); a01 = add2(a01, sp[1]);
            a10 = add2(a10, sp[2]); a11 = add2(a11, sp[3]);
            a20 = add2(a20, sp[4]); a21 = add2(a21, sp[5]);
            a30 = add2(a30, sp[6]); a31 = add2(a31, sp[7]);

            float gate[4][4];
            float2 p;
            p = upk2(a00); gate[0][0] = p.x; gate[0][1] = p.y;
            p = upk2(a01); gate[0][2] = p.x; gate[0][3] = p.y;
            p = upk2(a10); gate[1][0] = p.x; gate[1][1] = p.y;
            p = upk2(a11); gate[1][2] = p.x; gate[1][3] = p.y;
            p = upk2(a20); gate[2][0] = p.x; gate[2][1] = p.y;
            p = upk2(a21); gate[2][2] = p.x; gate[2][3] = p.y;
            p = upk2(a30); gate[3][0] = p.x; gate[3][1] = p.y;
            p = upk2(a31); gate[3][2] = p.x; gate[3][3] = p.y;

            const bool m = (t < len);
            float cc[4] = {c0, c1, c2, c3};
#pragma unroll
            for (int q = 0; q < 4; q++) {
                int uu = u0t + q;
                if (uu < kH) {
                    float iv = 1.f / (1.f + __expf(-gate[0][q]));
                    float fv = 1.f / (1.f + __expf(-gate[1][q]));
                    float gv = tanhf(gate[2][q]);
                    float ov = 1.f / (1.f + __expf(-gate[3][q]));
                    float cn = fv * cc[q] + iv * gv;
                    float hn = ov * tanhf(cn);
                    float hold = h_sm[bloc][uu];
                    if (m) cc[q] = cn;
                    float hw = m ? hn : hold;
                    __stcg(&g_h[parity ^ 1][dir][b][uu], hw);
                    outp[((size_t)b * kT + t) * 1000 + dir * kH + uu] = m ? hn : 0.f;
                } else {
                    __stcg(&g_h[parity ^ 1][dir][b][uu], 0.f);
                }
            }
            c0 = cc[0]; c1 = cc[1]; c2 = cc[2]; c3 = cc[3];
        }
        __threadfence();
        grid_bar();
    }
}

// --------------------------- launcher --------------------------------------
extern "C" void kernel_launch(void* const* d_in, const int* in_sizes, int n_in,
                              void* d_out, int out_size) {
    const float* seqs  = (const float*)d_in[0];
    const void*  lens  = d_in[1];
    const float* Wih0f = (const float*)d_in[2];
    const float* Whh0f = (const float*)d_in[3];
    const float* b0f   = (const float*)d_in[4];
    const float* Wih0b = (const float*)d_in[5];
    const float* Whh0b = (const float*)d_in[6];
    const float* b0b   = (const float*)d_in[7];
    const float* Wih1f = (const float*)d_in[8];
    const float* Whh1f = (const float*)d_in[9];
    const float* b1f   = (const float*)d_in[10];
    const float* Wih1b = (const float*)d_in[11];
    const float* Whh1b = (const float*)d_in[12];
    const float* b1b   = (const float*)d_in[13];
    float* out = (float*)d_out;

    k_len<<<1, 64>>>(lens);
    k_packW<<<16384, 256>>>(Whh0f, Whh0b, Whh1f, Whh1b);
    k_zero<<<512, 256>>>();

    dim3 gg(256, 16);
    // layer 0
    k_gemm<<<gg, 256>>>(seqs, 0, Wih0f, b0f, 0, 512);
    k_gemm<<<gg, 256>>>(seqs, 0, Wih0b, b0b, 1, 512);
    k_rnn<<<128, 256>>>(0, out);

    // layer 1
    k_zero<<<512, 256>>>();
    k_gemm<<<gg, 256>>>(nullptr, 1, Wih1f, b1f, 0, 1000);
    k_gemm<<<gg, 256>>>(nullptr, 1, Wih1b, b1b, 1, 1000);
    k_rnn<<<128, 256>>>(1, out);
}

// round 8
// speedup vs baseline: 1.8869x; 1.8869x over previous
#include <cuda_runtime.h>
#include <cstdint>
#include <math.h>

typedef unsigned long long ull;

static constexpr int kT = 512;
static constexpr int kB = 64;
static constexpr int kH = 500;

// ---------------- static device scratch (allocation-free) ----------------
// W_hh packed for SMEM residency: [dirIdx][ublock(32)][k(512)][64]
// slot = half*32 + p*4 + j ; gate g = half*2 + (j>>1); u = ub*16 + p*2 + (j&1)
__device__ float g_Wp[4][32][512][64];
__device__ float g_h[2][2][kB][512];                    // [parity][dir][b][u]
__device__ float g_gx0[(size_t)kB * kT * 2000];         // fwd input gates
__device__ float g_gx1[(size_t)kB * kT * 2000];         // bwd input gates
__device__ float g_out0[(size_t)kB * kT * 1000];        // layer-0 output
__device__ int   g_len[kB];
__device__ unsigned g_barcnt;                           // zero-init
__device__ volatile unsigned g_bargen;                  // zero-init

// ---------------- f32x2 helpers -------------------------------------------
__device__ __forceinline__ ull pk2(float lo, float hi) {
    ull r; asm("mov.b64 %0,{%1,%2};" : "=l"(r) : "f"(lo), "f"(hi)); return r;
}
__device__ __forceinline__ void fma2(ull& d, ull a, ull b) {
    asm("fma.rn.f32x2 %0,%1,%2,%0;" : "+l"(d) : "l"(a), "l"(b));
}
__device__ __forceinline__ float2 upk2(ull v) {
    float2 f; asm("mov.b64 {%0,%1},%2;" : "=f"(f.x), "=f"(f.y) : "l"(v)); return f;
}

// ---------------- lengths: int32 vs int64 detection ------------------------
__global__ void k_len(const void* __restrict__ lenraw) {
    const int* p32 = (const int*)lenraw;
    int i = threadIdx.x;
    // int64 LE: p32[1] = high word of lengths[0] = 0 (len in [1,512]); int32: p32[1] >= 1.
    int v = (p32[1] == 0) ? (int)((const long long*)lenraw)[i] : p32[i];
    if (i < kB) g_len[i] = v;
}

// ---------------- zero h (both parities, both dirs) ------------------------
__global__ void k_zero() {
    int i = blockIdx.x * 256 + threadIdx.x;              // 512*256 = 131072 = 2*2*64*512
    (&g_h[0][0][0][0])[i] = 0.f;
}

// ---------------- pack W_hh [2000][500] -> SMEM-friendly layout ------------
__global__ void k_packW(const float* __restrict__ w0f, const float* __restrict__ w0b,
                        const float* __restrict__ w1f, const float* __restrict__ w1b) {
    size_t i = (size_t)blockIdx.x * 256 + threadIdx.x;   // 4*32*512*64 = 4194304
    int slot = (int)(i & 63);
    int k    = (int)((i >> 6) & 511);
    int ub   = (int)((i >> 15) & 31);
    int d    = (int)(i >> 20);
    int half = slot >> 5;
    int p    = (slot >> 2) & 7;
    int j    = slot & 3;
    int g = half * 2 + (j >> 1);
    int u = ub * 16 + p * 2 + (j & 1);
    float v = 0.f;
    if (u < kH && k < kH) {
        const float* w = (d == 0) ? w0f : (d == 1) ? w0b : (d == 2) ? w1f : w1b;
        v = w[(size_t)(g * kH + u) * kH + k];
    }
    (&g_Wp[0][0][0][0])[i] = v;
}

// ---------------- input GEMM (f32x2): C[M,2000] = A[M,K] @ W[2000,K]^T + b --
__global__ void __launch_bounds__(256) k_gemm(
    const float* __restrict__ Aext, int useOut0,
    const float* __restrict__ W, const float* __restrict__ bias,
    int dstSel, int K)
{
    const float* __restrict__ A = useOut0 ? g_out0 : Aext;
    float* __restrict__ C = dstSel ? g_gx1 : g_gx0;

    __shared__ __align__(16) ull   AsD[8][128];  // dup-packed A, 8 KB
    __shared__ __align__(16) float Ws[8][128];   // 4 KB

    const int tid = threadIdx.x;
    const int m0 = blockIdx.x * 128;
    const int n0 = blockIdx.y * 128;
    const int lrow = tid >> 1;
    const int lk = (tid & 1) * 4;

    const float* aptr = A + (size_t)(m0 + lrow) * K + lk;
    const int wrow = n0 + lrow;
    const float* wptr = W + (size_t)wrow * K + lk;
    const bool wok = (wrow < 2000);

    ull acc[8][4];
#pragma unroll
    for (int i = 0; i < 8; i++)
#pragma unroll
        for (int j = 0; j < 4; j++) acc[i][j] = 0ULL;

    const int tx = tid & 15, ty = tid >> 4;

    for (int kc = 0; kc < K; kc += 8) {
        float4 av = *(const float4*)aptr; aptr += 8;
        float4 wv = wok ? *(const float4*)wptr : make_float4(0.f, 0.f, 0.f, 0.f);
        wptr += 8;
        __syncthreads();
        AsD[lk + 0][lrow] = pk2(av.x, av.x);
        AsD[lk + 1][lrow] = pk2(av.y, av.y);
        AsD[lk + 2][lrow] = pk2(av.z, av.z);
        AsD[lk + 3][lrow] = pk2(av.w, av.w);
        Ws[lk + 0][lrow] = wv.x; Ws[lk + 1][lrow] = wv.y;
        Ws[lk + 2][lrow] = wv.z; Ws[lk + 3][lrow] = wv.w;
        __syncthreads();
#pragma unroll
        for (int kk = 0; kk < 8; kk++) {
            ull a[8], w[4];
            const ull* ap = &AsD[kk][ty * 8];
#pragma unroll
            for (int i = 0; i < 8; i++) a[i] = ap[i];
            const ull* wp = (const ull*)&Ws[kk][tx * 8];
#pragma unroll
            for (int j = 0; j < 4; j++) w[j] = wp[j];
#pragma unroll
            for (int i = 0; i < 8; i++)
#pragma unroll
                for (int j = 0; j < 4; j++) fma2(acc[i][j], a[i], w[j]);
        }
    }
#pragma unroll
    for (int j = 0; j < 4; j++) {
        int n = n0 + tx * 8 + 2 * j;
        if (n >= 2000) continue;
        float b0 = bias[n];
        float b1 = (n + 1 < 2000) ? bias[n + 1] : 0.f;
#pragma unroll
        for (int i = 0; i < 8; i++) {
            int m = m0 + ty * 8 + i;
            float2 v = upk2(acc[i][j]);
            C[(size_t)m * 2000 + n] = v.x + b0;
            if (n + 1 < 2000) C[(size_t)m * 2000 + n + 1] = v.y + b1;
        }
    }
}

// ---------------- software grid barrier (128 CTAs, all co-resident) --------
__device__ __forceinline__ void grid_bar() {
    __syncthreads();
    if (threadIdx.x == 0) {
        unsigned my = g_bargen;
        __threadfence();
        unsigned old = atomicAdd(&g_barcnt, 1u);
        if (old == 127u) {
            g_barcnt = 0u;
            __threadfence();
            g_bargen = my + 1u;
        } else {
            while (g_bargen == my) { }
            __threadfence();
        }
    }
    __syncthreads();
}

// ---------------- persistent recurrence: W_hh resident in SMEM -------------
// 128 CTAs = dir(2) x ublock(32, 16 units) x bhalf(2, 32 batches).
// SMEM: W [512 k][64] = 128KB + h [32 b][516] = 66KB  -> 197120 B dynamic.
static constexpr int kRnnSmem = (512 * 64 + 32 * 516) * 4;

__global__ void __launch_bounds__(256) k_rnn(int layer, float* __restrict__ outExt)
{
    extern __shared__ float sm[];
    float* __restrict__ Wsm = sm;              // [512][64]
    float* __restrict__ hsm = sm + 512 * 64;   // [32][516] padded rows

    const int bid = blockIdx.x;
    const int dir = bid >> 6;
    const int ub  = (bid >> 1) & 31;
    const int bh  = bid & 1;
    const int tid = threadIdx.x;
    const int bl  = tid >> 3;          // 0..31 local batch
    const int p   = tid & 7;           // 0..7 unit-pair
    const int bg  = bh * 32 + bl;      // global batch
    const int u0  = ub * 16 + p * 2;   // unit-pair base
    const int dirIdx = layer * 2 + dir;

    // load W slice into SMEM once (128 KB)
    {
        const float4* src = (const float4*)&g_Wp[dirIdx][ub][0][0];
        float4* dst = (float4*)Wsm;
        for (int i = tid; i < 512 * 16; i += 256) dst[i] = src[i];
    }

    const float* __restrict__ gx = dir ? g_gx1 : g_gx0;
    float* __restrict__ outp = layer ? outExt : g_out0;
    const int len = g_len[bg];
    const bool uok = (u0 < kH);        // kH even, u0 even -> pair never straddles

    float c0 = 0.f, c1 = 0.f;          // cell state lives in registers

    const float* __restrict__ hp = hsm + bl * 516;
    const float* __restrict__ wp = Wsm + p * 4;

    for (int s = 0; s < kT; s++) {
        const int parity = s & 1;
        const int t = dir ? (kT - 1 - s) : s;

        // stage h_prev tile [32 b][512] into SMEM (L2-coherent loads)
        {
            const float4* src = (const float4*)&g_h[parity][dir][bh * 32][0];
            for (int i = tid; i < 32 * 128; i += 256) {
                float4 v = __ldcg(src + i);
                *(float4*)&hsm[(i >> 7) * 516 + (i & 127) * 4] = v;
            }
        }
        __syncthreads();

        ull a0, a1, a2, a3;
        if (uok) {
            const float* gxr = gx + ((size_t)bg * kT + t) * 2000 + u0;
            float2 v0 = *(const float2*)(gxr);
            float2 v1 = *(const float2*)(gxr + kH);
            float2 v2 = *(const float2*)(gxr + 2 * kH);
            float2 v3 = *(const float2*)(gxr + 3 * kH);
            a0 = pk2(v0.x, v0.y); a1 = pk2(v1.x, v1.y);
            a2 = pk2(v2.x, v2.y); a3 = pk2(v3.x, v3.y);
        } else {
            a0 = a1 = a2 = a3 = 0ULL;
        }

        // inner GEMV: all operands in SMEM, fma-pipe-bound
#pragma unroll 2
        for (int k4 = 0; k4 < 512; k4 += 4) {
            float4 hv = *(const float4*)(hp + k4);
#pragma unroll
            for (int kk = 0; kk < 4; kk++) {
                float hvv = (kk == 0) ? hv.x : (kk == 1) ? hv.y : (kk == 2) ? hv.z : hv.w;
                ull hd = pk2(hvv, hvv);
                const float* wk = wp + (k4 + kk) * 64;
                ulonglong2 wA = *(const ulonglong2*)(wk);        // gates 0,1
                ulonglong2 wB = *(const ulonglong2*)(wk + 32);   // gates 2,3
                fma2(a0, wA.x, hd);
                fma2(a1, wA.y, hd);
                fma2(a2, wB.x, hd);
                fma2(a3, wB.y, hd);
            }
        }

        if (uok) {
            float2 gi = upk2(a0), gf = upk2(a1), gg = upk2(a2), go = upk2(a3);
            const bool m = (t < len);

            float i0 = 1.f / (1.f + __expf(-gi.x));
            float i1 = 1.f / (1.f + __expf(-gi.y));
            float f0 = 1.f / (1.f + __expf(-gf.x));
            float f1 = 1.f / (1.f + __expf(-gf.y));
            float g0 = tanhf(gg.x);
            float g1 = tanhf(gg.y);
            float o0 = 1.f / (1.f + __expf(-go.x));
            float o1 = 1.f / (1.f + __expf(-go.y));

            float cn0 = f0 * c0 + i0 * g0;
            float cn1 = f1 * c1 + i1 * g1;
            float hn0 = o0 * tanhf(cn0);
            float hn1 = o1 * tanhf(cn1);
            float ho0 = hp[u0];
            float ho1 = hp[u0 + 1];
            if (m) { c0 = cn0; c1 = cn1; }
            float hw0 = m ? hn0 : ho0;
            float hw1 = m ? hn1 : ho1;
            __stcg(&g_h[parity ^ 1][dir][bg][u0], hw0);
            __stcg(&g_h[parity ^ 1][dir][bg][u0 + 1], hw1);
            size_t oidx = ((size_t)bg * kT + t) * 1000 + dir * kH + u0;
            outp[oidx]     = m ? hn0 : 0.f;
            outp[oidx + 1] = m ? hn1 : 0.f;
        }
        __threadfence();
        grid_bar();
    }
}

// --------------------------- launcher --------------------------------------
extern "C" void kernel_launch(void* const* d_in, const int* in_sizes, int n_in,
                              void* d_out, int out_size) {
    const float* seqs  = (const float*)d_in[0];
    const void*  lens  = d_in[1];
    const float* Wih0f = (const float*)d_in[2];
    const float* Whh0f = (const float*)d_in[3];
    const float* b0f   = (const float*)d_in[4];
    const float* Wih0b = (const float*)d_in[5];
    const float* Whh0b = (const float*)d_in[6];
    const float* b0b   = (const float*)d_in[7];
    const float* Wih1f = (const float*)d_in[8];
    const float* Whh1f = (const float*)d_in[9];
    const float* b1f   = (const float*)d_in[10];
    const float* Wih1b = (const float*)d_in[11];
    const float* Whh1b = (const float*)d_in[12];
    const float* b1b   = (const float*)d_in[13];
    float* out = (float*)d_out;

    cudaFuncSetAttribute(k_rnn, cudaFuncAttributeMaxDynamicSharedMemorySize, kRnnSmem);

    k_len<<<1, 64>>>(lens);
    k_packW<<<16384, 256>>>(Whh0f, Whh0b, Whh1f, Whh1b);
    k_zero<<<512, 256>>>();

    dim3 gg(256, 16);
    // layer 0
    k_gemm<<<gg, 256>>>(seqs, 0, Wih0f, b0f, 0, 512);
    k_gemm<<<gg, 256>>>(seqs, 0, Wih0b, b0b, 1, 512);
    k_rnn<<<128, 256, kRnnSmem>>>(0, out);

    // layer 1
    k_zero<<<512, 256>>>();
    k_gemm<<<gg, 256>>>(nullptr, 1, Wih1f, b1f, 0, 1000);
    k_gemm<<<gg, 256>>>(nullptr, 1, Wih1b, b1b, 1, 1000);
    k_rnn<<<128, 256, kRnnSmem>>>(1, out);
}

// round 9
// speedup vs baseline: 2.0087x; 1.0645x over previous
#include <cuda_runtime.h>
#include <cstdint>
#include <math.h>

typedef unsigned long long ull;

static constexpr int kT = 512;
static constexpr int kB = 64;
static constexpr int kH = 500;

// ---------------- static device scratch (allocation-free) ----------------
// W_hh packed for SMEM residency: [dirIdx][ublock(32)][k(512)][64]
// slot = half*32 + p*4 + j ; gate g = half*2 + (j>>1); u = ub*16 + p*2 + (j&1)
__device__ float g_Wp[4][32][512][64];
__device__ float g_h[2][2][kB][512];                    // [parity][dir][b][u]
__device__ float g_gx0[(size_t)kB * kT * 2000];         // fwd input gates
__device__ float g_gx1[(size_t)kB * kT * 2000];         // bwd input gates
__device__ float g_out0[(size_t)kB * kT * 1000];        // layer-0 output
__device__ int   g_len[kB];
// 4 independent barrier groups (dir x bhalf), each 32 CTAs; padded to 128B
__device__ unsigned g_barcnt4[4][32];
__device__ volatile unsigned g_bargen4[4][32];

// ---------------- f32x2 helpers -------------------------------------------
__device__ __forceinline__ ull pk2(float lo, float hi) {
    ull r; asm("mov.b64 %0,{%1,%2};" : "=l"(r) : "f"(lo), "f"(hi)); return r;
}
__device__ __forceinline__ void fma2(ull& d, ull a, ull b) {
    asm("fma.rn.f32x2 %0,%1,%2,%0;" : "+l"(d) : "l"(a), "l"(b));
}
__device__ __forceinline__ float2 upk2(ull v) {
    float2 f; asm("mov.b64 {%0,%1},%2;" : "=f"(f.x), "=f"(f.y) : "l"(v)); return f;
}

// ---------------- lengths: int32 vs int64 detection ------------------------
__global__ void k_len(const void* __restrict__ lenraw) {
    const int* p32 = (const int*)lenraw;
    int i = threadIdx.x;
    // int64 LE: p32[1] = high word of lengths[0] = 0 (len in [1,512]); int32: p32[1] >= 1.
    int v = (p32[1] == 0) ? (int)((const long long*)lenraw)[i] : p32[i];
    if (i < kB) g_len[i] = v;
}

// ---------------- zero h (both parities, both dirs) ------------------------
__global__ void k_zero() {
    int i = blockIdx.x * 256 + threadIdx.x;              // 512*256 = 131072 = 2*2*64*512
    (&g_h[0][0][0][0])[i] = 0.f;
}

// ---------------- pack W_hh [2000][500] -> SMEM-friendly layout ------------
__global__ void k_packW(const float* __restrict__ w0f, const float* __restrict__ w0b,
                        const float* __restrict__ w1f, const float* __restrict__ w1b) {
    size_t i = (size_t)blockIdx.x * 256 + threadIdx.x;   // 4*32*512*64 = 4194304
    int slot = (int)(i & 63);
    int k    = (int)((i >> 6) & 511);
    int ub   = (int)((i >> 15) & 31);
    int d    = (int)(i >> 20);
    int half = slot >> 5;
    int p    = (slot >> 2) & 7;
    int j    = slot & 3;
    int g = half * 2 + (j >> 1);
    int u = ub * 16 + p * 2 + (j & 1);
    float v = 0.f;
    if (u < kH && k < kH) {
        const float* w = (d == 0) ? w0f : (d == 1) ? w0b : (d == 2) ? w1f : w1b;
        v = w[(size_t)(g * kH + u) * kH + k];
    }
    (&g_Wp[0][0][0][0])[i] = v;
}

// ---------------- input GEMM (f32x2, double-buffered) ----------------------
// C[M,2000] = A[M,K] @ W[2000,K]^T + bias
__global__ void __launch_bounds__(256, 2) k_gemm(
    const float* __restrict__ Aext, int useOut0,
    const float* __restrict__ W, const float* __restrict__ bias,
    int dstSel, int K)
{
    const float* __restrict__ A = useOut0 ? g_out0 : Aext;
    float* __restrict__ C = dstSel ? g_gx1 : g_gx0;

    __shared__ __align__(16) ull   AsD[2][8][128];  // dup-packed A, 16 KB
    __shared__ __align__(16) float Ws[2][8][128];   // 8 KB

    const int tid = threadIdx.x;
    const int m0 = blockIdx.x * 128;
    const int n0 = blockIdx.y * 128;
    const int lrow = tid >> 1;
    const int lk = (tid & 1) * 4;

    const float* aptr = A + (size_t)(m0 + lrow) * K + lk;
    const int wrow = n0 + lrow;
    const float* wptr = W + (size_t)wrow * K + lk;
    const bool wok = (wrow < 2000);
    const int ntiles = K >> 3;

    ull acc[8][4];
#pragma unroll
    for (int i = 0; i < 8; i++)
#pragma unroll
        for (int j = 0; j < 4; j++) acc[i][j] = 0ULL;

    const int tx = tid & 15, ty = tid >> 4;

    // prologue: tile 0 -> stage 0; prefetch tile 1 into regs
    {
        float4 av = *(const float4*)aptr; aptr += 8;
        float4 wv = wok ? *(const float4*)wptr : make_float4(0.f, 0.f, 0.f, 0.f);
        wptr += 8;
        AsD[0][lk + 0][lrow] = pk2(av.x, av.x);
        AsD[0][lk + 1][lrow] = pk2(av.y, av.y);
        AsD[0][lk + 2][lrow] = pk2(av.z, av.z);
        AsD[0][lk + 3][lrow] = pk2(av.w, av.w);
        Ws[0][lk + 0][lrow] = wv.x; Ws[0][lk + 1][lrow] = wv.y;
        Ws[0][lk + 2][lrow] = wv.z; Ws[0][lk + 3][lrow] = wv.w;
    }
    float4 av1 = make_float4(0.f, 0.f, 0.f, 0.f), wv1 = av1;
    if (ntiles > 1) {
        av1 = *(const float4*)aptr; aptr += 8;
        if (wok) wv1 = *(const float4*)wptr;
        wptr += 8;
    }
    __syncthreads();

    for (int tile = 0; tile < ntiles; tile++) {
        const int cur = tile & 1, nxt = cur ^ 1;
        if (tile + 1 < ntiles) {
            AsD[nxt][lk + 0][lrow] = pk2(av1.x, av1.x);
            AsD[nxt][lk + 1][lrow] = pk2(av1.y, av1.y);
            AsD[nxt][lk + 2][lrow] = pk2(av1.z, av1.z);
            AsD[nxt][lk + 3][lrow] = pk2(av1.w, av1.w);
            Ws[nxt][lk + 0][lrow] = wv1.x; Ws[nxt][lk + 1][lrow] = wv1.y;
            Ws[nxt][lk + 2][lrow] = wv1.z; Ws[nxt][lk + 3][lrow] = wv1.w;
        }
        if (tile + 2 < ntiles) {
            av1 = *(const float4*)aptr; aptr += 8;
            wv1 = wok ? *(const float4*)wptr : make_float4(0.f, 0.f, 0.f, 0.f);
            wptr += 8;
        }
#pragma unroll
        for (int kk = 0; kk < 8; kk++) {
            ull a[8], w[4];
            const ull* ap = &AsD[cur][kk][ty * 8];
#pragma unroll
            for (int i = 0; i < 8; i++) a[i] = ap[i];
            const ull* wp = (const ull*)&Ws[cur][kk][tx * 8];
#pragma unroll
            for (int j = 0; j < 4; j++) w[j] = wp[j];
#pragma unroll
            for (int i = 0; i < 8; i++)
#pragma unroll
                for (int j = 0; j < 4; j++) fma2(acc[i][j], a[i], w[j]);
        }
        __syncthreads();
    }
#pragma unroll
    for (int j = 0; j < 4; j++) {
        int n = n0 + tx * 8 + 2 * j;
        if (n >= 2000) continue;
        float b0 = bias[n];
        float b1 = (n + 1 < 2000) ? bias[n + 1] : 0.f;
#pragma unroll
        for (int i = 0; i < 8; i++) {
            int m = m0 + ty * 8 + i;
            float2 v = upk2(acc[i][j]);
            C[(size_t)m * 2000 + n] = v.x + b0;
            if (n + 1 < 2000) C[(size_t)m * 2000 + n + 1] = v.y + b1;
        }
    }
}

// ---------------- software barrier for a 32-CTA group ----------------------
__device__ __forceinline__ void grid_bar(int gid) {
    __syncthreads();
    if (threadIdx.x == 0) {
        unsigned my = g_bargen4[gid][0];
        __threadfence();
        unsigned old = atomicAdd(&g_barcnt4[gid][0], 1u);
        if (old == 31u) {
            g_barcnt4[gid][0] = 0u;
            __threadfence();
            g_bargen4[gid][0] = my + 1u;
        } else {
            while (g_bargen4[gid][0] == my) { }
            __threadfence();
        }
    }
    __syncthreads();
}

// ---------------- persistent recurrence: W_hh resident in SMEM -------------
// 128 CTAs = dir(2) x ublock(32, 16 units) x bhalf(2, 32 batches).
// Sync only within (dir, bhalf) groups of 32 CTAs.
static constexpr int kRnnSmem = (512 * 64 + 32 * 516) * 4;

__global__ void __launch_bounds__(256) k_rnn(int layer, float* __restrict__ outExt)
{
    extern __shared__ float sm[];
    float* __restrict__ Wsm = sm;              // [512][64]
    float* __restrict__ hsm = sm + 512 * 64;   // [32][516] padded rows

    const int bid = blockIdx.x;
    const int dir = bid >> 6;
    const int ub  = (bid >> 1) & 31;
    const int bh  = bid & 1;
    const int gid = dir * 2 + bh;
    const int tid = threadIdx.x;
    const int bl  = tid >> 3;          // 0..31 local batch
    const int p   = tid & 7;           // 0..7 unit-pair
    const int bg  = bh * 32 + bl;      // global batch
    const int u0  = ub * 16 + p * 2;   // unit-pair base
    const int dirIdx = layer * 2 + dir;

    // load W slice into SMEM once (128 KB)
    {
        const float4* src = (const float4*)&g_Wp[dirIdx][ub][0][0];
        float4* dst = (float4*)Wsm;
        for (int i = tid; i < 512 * 16; i += 256) dst[i] = src[i];
    }

    const float* __restrict__ gx = dir ? g_gx1 : g_gx0;
    float* __restrict__ outp = layer ? outExt : g_out0;
    const int len = g_len[bg];
    const bool uok = (u0 < kH);

    float c0 = 0.f, c1 = 0.f;          // cell state lives in registers

    const float* __restrict__ hp = hsm + bl * 516;
    const float* __restrict__ wp = Wsm + p * 4;

    // software pipeline: preload gx for s=0
    float2 v0, v1, v2, v3;
    if (uok) {
        int t0 = dir ? (kT - 1) : 0;
        const float* r = gx + ((size_t)bg * kT + t0) * 2000 + u0;
        v0 = *(const float2*)(r);
        v1 = *(const float2*)(r + kH);
        v2 = *(const float2*)(r + 2 * kH);
        v3 = *(const float2*)(r + 3 * kH);
    }

    for (int s = 0; s < kT; s++) {
        const int parity = s & 1;
        const int t = dir ? (kT - 1 - s) : s;

        // stage h_prev tile [32 b][512] into SMEM (L2-coherent loads)
        {
            const float4* src = (const float4*)&g_h[parity][dir][bh * 32][0];
            for (int i = tid; i < 32 * 128; i += 256) {
                float4 v = __ldcg(src + i);
                *(float4*)&hsm[(i >> 7) * 516 + (i & 127) * 4] = v;
            }
        }
        __syncthreads();

        ull a0, a1, a2, a3;
        if (uok) {
            a0 = pk2(v0.x, v0.y); a1 = pk2(v1.x, v1.y);
            a2 = pk2(v2.x, v2.y); a3 = pk2(v3.x, v3.y);
        } else {
            a0 = a1 = a2 = a3 = 0ULL;
        }

        // inner GEMV: all operands in SMEM
#pragma unroll 2
        for (int k4 = 0; k4 < 512; k4 += 4) {
            float4 hv = *(const float4*)(hp + k4);
#pragma unroll
            for (int kk = 0; kk < 4; kk++) {
                float hvv = (kk == 0) ? hv.x : (kk == 1) ? hv.y : (kk == 2) ? hv.z : hv.w;
                ull hd = pk2(hvv, hvv);
                const float* wk = wp + (k4 + kk) * 64;
                ulonglong2 wA = *(const ulonglong2*)(wk);        // gates 0,1
                ulonglong2 wB = *(const ulonglong2*)(wk + 32);   // gates 2,3
                fma2(a0, wA.x, hd);
                fma2(a1, wA.y, hd);
                fma2(a2, wB.x, hd);
                fma2(a3, wB.y, hd);
            }
        }

        if (uok) {
            float2 gi = upk2(a0), gf = upk2(a1), gg = upk2(a2), go = upk2(a3);
            const bool m = (t < len);

            float i0 = 1.f / (1.f + __expf(-gi.x));
            float i1 = 1.f / (1.f + __expf(-gi.y));
            float f0 = 1.f / (1.f + __expf(-gf.x));
            float f1 = 1.f / (1.f + __expf(-gf.y));
            float g0 = tanhf(gg.x);
            float g1 = tanhf(gg.y);
            float o0 = 1.f / (1.f + __expf(-go.x));
            float o1 = 1.f / (1.f + __expf(-go.y));

            float cn0 = f0 * c0 + i0 * g0;
            float cn1 = f1 * c1 + i1 * g1;
            float hn0 = o0 * tanhf(cn0);
            float hn1 = o1 * tanhf(cn1);
            float ho0 = hp[u0];
            float ho1 = hp[u0 + 1];
            if (m) { c0 = cn0; c1 = cn1; }
            float hw0 = m ? hn0 : ho0;
            float hw1 = m ? hn1 : ho1;
            __stcg(&g_h[parity ^ 1][dir][bg][u0], hw0);
            __stcg(&g_h[parity ^ 1][dir][bg][u0 + 1], hw1);
            size_t oidx = ((size_t)bg * kT + t) * 1000 + dir * kH + u0;
            outp[oidx]     = m ? hn0 : 0.f;
            outp[oidx + 1] = m ? hn1 : 0.f;

            // prefetch next step's gx (overlaps with barrier wait)
            if (s + 1 < kT) {
                int tn = dir ? (kT - 2 - s) : (s + 1);
                const float* r = gx + ((size_t)bg * kT + tn) * 2000 + u0;
                v0 = *(const float2*)(r);
                v1 = *(const float2*)(r + kH);
                v2 = *(const float2*)(r + 2 * kH);
                v3 = *(const float2*)(r + 3 * kH);
            }
        }
        grid_bar(gid);
    }
}

// --------------------------- launcher --------------------------------------
extern "C" void kernel_launch(void* const* d_in, const int* in_sizes, int n_in,
                              void* d_out, int out_size) {
    const float* seqs  = (const float*)d_in[0];
    const void*  lens  = d_in[1];
    const float* Wih0f = (const float*)d_in[2];
    const float* Whh0f = (const float*)d_in[3];
    const float* b0f   = (const float*)d_in[4];
    const float* Wih0b = (const float*)d_in[5];
    const float* Whh0b = (const float*)d_in[6];
    const float* b0b   = (const float*)d_in[7];
    const float* Wih1f = (const float*)d_in[8];
    const float* Whh1f = (const float*)d_in[9];
    const float* b1f   = (const float*)d_in[10];
    const float* Wih1b = (const float*)d_in[11];
    const float* Whh1b = (const float*)d_in[12];
    const float* b1b   = (const float*)d_in[13];
    float* out = (float*)d_out;

    cudaFuncSetAttribute(k_rnn, cudaFuncAttributeMaxDynamicSharedMemorySize, kRnnSmem);

    k_len<<<1, 64>>>(lens);
    k_packW<<<16384, 256>>>(Whh0f, Whh0b, Whh1f, Whh1b);
    k_zero<<<512, 256>>>();

    dim3 gg(256, 16);
    // layer 0
    k_gemm<<<gg, 256>>>(seqs, 0, Wih0f, b0f, 0, 512);
    k_gemm<<<gg, 256>>>(seqs, 0, Wih0b, b0b, 1, 512);
    k_rnn<<<128, 256, kRnnSmem>>>(0, out);

    // layer 1
    k_zero<<<512, 256>>>();
    k_gemm<<<gg, 256>>>(nullptr, 1, Wih1f, b1f, 0, 1000);
    k_gemm<<<gg, 256>>>(nullptr, 1, Wih1b, b1b, 1, 1000);
    k_rnn<<<128, 256, kRnnSmem>>>(1, out);
}

// round 10
// speedup vs baseline: 2.0602x; 1.0257x over previous
#include <cuda_runtime.h>
#include <cstdint>
#include <math.h>

typedef unsigned long long ull;

static constexpr int kT = 512;
static constexpr int kB = 64;
static constexpr int kH = 500;

// ---------------- static device scratch (allocation-free) ----------------
// W_hh packed for SMEM residency: [dirIdx][ublock(32)][k(512)][64]
// slot = half*32 + p*4 + j ; gate g = half*2 + (j>>1); u = ub*16 + p*2 + (j&1)
__device__ float g_Wp[4][32][512][64];
__device__ float g_h[2][2][kB][512];                    // [parity][dir][b][u]
__device__ float g_gx0[(size_t)kB * kT * 2000];         // fwd input gates
__device__ float g_gx1[(size_t)kB * kT * 2000];         // bwd input gates
__device__ float g_out0[(size_t)kB * kT * 1024];        // layer-0 output, stride 1024 (padded)
__device__ float g_Wi1[2][2000][1024];                  // padded W_ih layer-1 (f,b)
__device__ int   g_len[kB];
__device__ int   g_flag[4][32];                         // per-(dir,bhalf) group, per-ublock step tags

// ---------------- f32x2 helpers -------------------------------------------
__device__ __forceinline__ ull pk2(float lo, float hi) {
    ull r; asm("mov.b64 %0,{%1,%2};" : "=l"(r) : "f"(lo), "f"(hi)); return r;
}
__device__ __forceinline__ void fma2(ull& d, ull a, ull b) {
    asm("fma.rn.f32x2 %0,%1,%2,%0;" : "+l"(d) : "l"(a), "l"(b));
}
__device__ __forceinline__ float2 upk2(ull v) {
    float2 f; asm("mov.b64 {%0,%1},%2;" : "=f"(f.x), "=f"(f.y) : "l"(v)); return f;
}
__device__ __forceinline__ int ldpoll(const int* p) {
    int v; asm volatile("ld.global.cg.b32 %0,[%1];" : "=r"(v) : "l"(p) : "memory"); return v;
}
__device__ __forceinline__ void stflag(int* p, int v) {
    asm volatile("st.global.cg.b32 [%0],%1;" :: "l"(p), "r"(v) : "memory");
}

// ---------------- lengths + flag reset -------------------------------------
__global__ void k_len(const void* __restrict__ lenraw) {
    const int* p32 = (const int*)lenraw;
    int i = threadIdx.x;
    if (i < kB) {
        // int64 LE: p32[1] = high word of lengths[0] = 0 (len in [1,512]); int32: p32[1] >= 1.
        int v = (p32[1] == 0) ? (int)((const long long*)lenraw)[i] : p32[i];
        g_len[i] = v;
    } else if (i < kB + 128) {
        int j = i - kB;
        g_flag[j >> 5][j & 31] = 0;
    }
}

// ---------------- zero h (both parities, both dirs) ------------------------
__global__ void k_zero() {
    int i = blockIdx.x * 256 + threadIdx.x;              // 512*256 = 131072 = 2*2*64*512
    (&g_h[0][0][0][0])[i] = 0.f;
}

// ---------------- zero the pad columns of g_out0 ---------------------------
__global__ void k_zpad() {
    int i = blockIdx.x * 256 + threadIdx.x;              // 3072*256 = 786432 = 32768*24
    int row = i / 24, p = i % 24;
    g_out0[(size_t)row * 1024 + 1000 + p] = 0.f;
}

// ---------------- pad W_ih layer-1 [2000][1000] -> [2000][1024] ------------
__global__ void k_padWih(const float* __restrict__ wf, const float* __restrict__ wb) {
    size_t i = (size_t)blockIdx.x * 256 + threadIdx.x;   // 2*2000*1024 = 4,096,000
    int k = (int)(i & 1023);
    int n = (int)((i >> 10) % 2000);
    int d = (int)(i / (2000 * 1024));
    const float* src = d ? wb : wf;
    g_Wi1[d][n][k] = (k < 1000) ? src[(size_t)n * 1000 + k] : 0.f;
}

// ---------------- pack W_hh [2000][500] -> SMEM-friendly layout ------------
__global__ void k_packW(const float* __restrict__ w0f, const float* __restrict__ w0b,
                        const float* __restrict__ w1f, const float* __restrict__ w1b) {
    size_t i = (size_t)blockIdx.x * 256 + threadIdx.x;   // 4*32*512*64 = 4194304
    int slot = (int)(i & 63);
    int k    = (int)((i >> 6) & 511);
    int ub   = (int)((i >> 15) & 31);
    int d    = (int)(i >> 20);
    int half = slot >> 5;
    int p    = (slot >> 2) & 7;
    int j    = slot & 3;
    int g = half * 2 + (j >> 1);
    int u = ub * 16 + p * 2 + (j & 1);
    float v = 0.f;
    if (u < kH && k < kH) {
        const float* w = (d == 0) ? w0f : (d == 1) ? w0b : (d == 2) ? w1f : w1b;
        v = w[(size_t)(g * kH + u) * kH + k];
    }
    (&g_Wp[0][0][0][0])[i] = v;
}

// ---------------- input GEMM (f32x2, double-buffered, 16-k chunks) ---------
// C[M,2000] = A[M,K] @ W[2000,K]^T + bias.  K % 16 == 0.
// aSel: 0 = Aext, 1 = g_out0.  wSel: 0 = Wext, 1 = g_Wi1[0], 2 = g_Wi1[1].
__global__ void __launch_bounds__(256, 2) k_gemm(
    const float* __restrict__ Aext, int aSel,
    const float* __restrict__ Wext, int wSel,
    const float* __restrict__ bias, int dstSel, int K)
{
    const float* __restrict__ A = aSel ? g_out0 : Aext;
    const float* __restrict__ W = (wSel == 0) ? Wext : &g_Wi1[wSel - 1][0][0];
    float* __restrict__ C = dstSel ? g_gx1 : g_gx0;

    __shared__ __align__(16) ull   AsD[2][16][128];  // dup-packed A, 32 KB
    __shared__ __align__(16) float Ws[2][16][128];   // 16 KB

    const int tid = threadIdx.x;
    const int m0 = blockIdx.x * 128;
    const int n0 = blockIdx.y * 128;
    const int lrow = tid >> 1;
    const int lkh = (tid & 1) * 8;

    const float* aptr = A + (size_t)(m0 + lrow) * K + lkh;
    const int wrow = n0 + lrow;
    const float* wptr = W + (size_t)wrow * K + lkh;
    const bool wok = (wrow < 2000);
    const int nch = K >> 4;

    ull acc[8][4];
#pragma unroll
    for (int i = 0; i < 8; i++)
#pragma unroll
        for (int j = 0; j < 4; j++) acc[i][j] = 0ULL;

    const int tx = tid & 15, ty = tid >> 4;

    // prologue: chunk 0 -> buf 0
    {
        float4 a0 = *(const float4*)aptr;
        float4 a1 = *(const float4*)(aptr + 4);
        float4 w0 = wok ? *(const float4*)wptr : make_float4(0.f, 0.f, 0.f, 0.f);
        float4 w1 = wok ? *(const float4*)(wptr + 4) : make_float4(0.f, 0.f, 0.f, 0.f);
        aptr += 16; wptr += 16;
        AsD[0][lkh + 0][lrow] = pk2(a0.x, a0.x);
        AsD[0][lkh + 1][lrow] = pk2(a0.y, a0.y);
        AsD[0][lkh + 2][lrow] = pk2(a0.z, a0.z);
        AsD[0][lkh + 3][lrow] = pk2(a0.w, a0.w);
        AsD[0][lkh + 4][lrow] = pk2(a1.x, a1.x);
        AsD[0][lkh + 5][lrow] = pk2(a1.y, a1.y);
        AsD[0][lkh + 6][lrow] = pk2(a1.z, a1.z);
        AsD[0][lkh + 7][lrow] = pk2(a1.w, a1.w);
        Ws[0][lkh + 0][lrow] = w0.x; Ws[0][lkh + 1][lrow] = w0.y;
        Ws[0][lkh + 2][lrow] = w0.z; Ws[0][lkh + 3][lrow] = w0.w;
        Ws[0][lkh + 4][lrow] = w1.x; Ws[0][lkh + 5][lrow] = w1.y;
        Ws[0][lkh + 6][lrow] = w1.z; Ws[0][lkh + 7][lrow] = w1.w;
    }
    float4 pa0 = make_float4(0.f, 0.f, 0.f, 0.f), pa1 = pa0, pw0 = pa0, pw1 = pa0;
    if (nch > 1) {
        pa0 = *(const float4*)aptr;
        pa1 = *(const float4*)(aptr + 4);
        if (wok) { pw0 = *(const float4*)wptr; pw1 = *(const float4*)(wptr + 4); }
        aptr += 16; wptr += 16;
    }
    __syncthreads();

    for (int ch = 0; ch < nch; ch++) {
        const int cur = ch & 1, nxt = cur ^ 1;
        if (ch + 1 < nch) {
            AsD[nxt][lkh + 0][lrow] = pk2(pa0.x, pa0.x);
            AsD[nxt][lkh + 1][lrow] = pk2(pa0.y, pa0.y);
            AsD[nxt][lkh + 2][lrow] = pk2(pa0.z, pa0.z);
            AsD[nxt][lkh + 3][lrow] = pk2(pa0.w, pa0.w);
            AsD[nxt][lkh + 4][lrow] = pk2(pa1.x, pa1.x);
            AsD[nxt][lkh + 5][lrow] = pk2(pa1.y, pa1.y);
            AsD[nxt][lkh + 6][lrow] = pk2(pa1.z, pa1.z);
            AsD[nxt][lkh + 7][lrow] = pk2(pa1.w, pa1.w);
            Ws[nxt][lkh + 0][lrow] = pw0.x; Ws[nxt][lkh + 1][lrow] = pw0.y;
            Ws[nxt][lkh + 2][lrow] = pw0.z; Ws[nxt][lkh + 3][lrow] = pw0.w;
            Ws[nxt][lkh + 4][lrow] = pw1.x; Ws[nxt][lkh + 5][lrow] = pw1.y;
            Ws[nxt][lkh + 6][lrow] = pw1.z; Ws[nxt][lkh + 7][lrow] = pw1.w;
        }
        if (ch + 2 < nch) {
            pa0 = *(const float4*)aptr;
            pa1 = *(const float4*)(aptr + 4);
            pw0 = wok ? *(const float4*)wptr : make_float4(0.f, 0.f, 0.f, 0.f);
            pw1 = wok ? *(const float4*)(wptr + 4) : make_float4(0.f, 0.f, 0.f, 0.f);
            aptr += 16; wptr += 16;
        }
#pragma unroll
        for (int kk = 0; kk < 16; kk++) {
            ull a[8], w[4];
            const ull* ap = &AsD[cur][kk][ty * 8];
#pragma unroll
            for (int i = 0; i < 8; i++) a[i] = ap[i];
            const ull* wp = (const ull*)&Ws[cur][kk][tx * 8];
#pragma unroll
            for (int j = 0; j < 4; j++) w[j] = wp[j];
#pragma unroll
            for (int i = 0; i < 8; i++)
#pragma unroll
                for (int j = 0; j < 4; j++) fma2(acc[i][j], a[i], w[j]);
        }
        __syncthreads();
    }
#pragma unroll
    for (int j = 0; j < 4; j++) {
        int n = n0 + tx * 8 + 2 * j;
        if (n >= 2000) continue;
        float b0 = bias[n];
        float b1 = (n + 1 < 2000) ? bias[n + 1] : 0.f;
#pragma unroll
        for (int i = 0; i < 8; i++) {
            int m = m0 + ty * 8 + i;
            float2 v = upk2(acc[i][j]);
            C[(size_t)m * 2000 + n] = v.x + b0;
            if (n + 1 < 2000) C[(size_t)m * 2000 + n + 1] = v.y + b1;
        }
    }
}

// ---------------- persistent recurrence: W_hh resident in SMEM -------------
// 128 CTAs = dir(2) x ublock(32, 16 units) x bhalf(2, 32 batches).
// Sync within (dir, bhalf) groups of 32 CTAs via per-producer flags.
static constexpr int kRnnSmem = (512 * 64 + 32 * 516) * 4;

__global__ void __launch_bounds__(256) k_rnn(int layer, float* __restrict__ outExt)
{
    extern __shared__ float sm[];
    float* __restrict__ Wsm = sm;              // [512][64]
    float* __restrict__ hsm = sm + 512 * 64;   // [32][516] padded rows

    const int bid = blockIdx.x;
    const int dir = bid >> 6;
    const int ub  = (bid >> 1) & 31;
    const int bh  = bid & 1;
    const int gid = dir * 2 + bh;
    const int tid = threadIdx.x;
    const int bl  = tid >> 3;          // 0..31 local batch
    const int p   = tid & 7;           // 0..7 unit-pair
    const int bg  = bh * 32 + bl;      // global batch
    const int u0  = ub * 16 + p * 2;   // unit-pair base
    const int dirIdx = layer * 2 + dir;

    // load W slice into SMEM once (128 KB)
    {
        const float4* src = (const float4*)&g_Wp[dirIdx][ub][0][0];
        float4* dst = (float4*)Wsm;
        for (int i = tid; i < 512 * 16; i += 256) dst[i] = src[i];
    }

    const float* __restrict__ gx = dir ? g_gx1 : g_gx0;
    float* __restrict__ outp = layer ? outExt : g_out0;
    const int ostride = layer ? 1000 : 1024;
    const int len = g_len[bg];
    const bool uok = (u0 < kH);

    float c0 = 0.f, c1 = 0.f;          // cell state lives in registers

    const float* __restrict__ hp = hsm + bl * 516;
    const float* __restrict__ wp = Wsm + p * 4;

    // software pipeline: preload gx for s=0
    float2 v0, v1, v2, v3;
    if (uok) {
        int t0 = dir ? (kT - 1) : 0;
        const float* r = gx + ((size_t)bg * kT + t0) * 2000 + u0;
        v0 = *(const float2*)(r);
        v1 = *(const float2*)(r + kH);
        v2 = *(const float2*)(r + 2 * kH);
        v3 = *(const float2*)(r + 3 * kH);
    }

    for (int s = 0; s < kT; s++) {
        const int parity = s & 1;
        const int t = dir ? (kT - 1 - s) : s;
        const int tag = layer * kT + s;

        // wait for all 32 producers of this group to have published step tag
        if (tid < 32) {
            const int* fl = &g_flag[gid][tid];
            while (ldpoll(fl) < tag) { }
            __threadfence();
        }
        __syncthreads();

        // stage h_prev tile [32 b][512] into SMEM (L2-coherent loads)
        {
            const float4* src = (const float4*)&g_h[parity][dir][bh * 32][0];
            for (int i = tid; i < 32 * 128; i += 256) {
                float4 v = __ldcg(src + i);
                *(float4*)&hsm[(i >> 7) * 516 + (i & 127) * 4] = v;
            }
        }
        __syncthreads();

        ull a0, a1, a2, a3;
        if (uok) {
            a0 = pk2(v0.x, v0.y); a1 = pk2(v1.x, v1.y);
            a2 = pk2(v2.x, v2.y); a3 = pk2(v3.x, v3.y);
        } else {
            a0 = a1 = a2 = a3 = 0ULL;
        }

        // inner GEMV: all operands in SMEM
#pragma unroll 4
        for (int k4 = 0; k4 < 512; k4 += 4) {
            float4 hv = *(const float4*)(hp + k4);
#pragma unroll
            for (int kk = 0; kk < 4; kk++) {
                float hvv = (kk == 0) ? hv.x : (kk == 1) ? hv.y : (kk == 2) ? hv.z : hv.w;
                ull hd = pk2(hvv, hvv);
                const float* wk = wp + (k4 + kk) * 64;
                ulonglong2 wA = *(const ulonglong2*)(wk);        // gates 0,1
                ulonglong2 wB = *(const ulonglong2*)(wk + 32);   // gates 2,3
                fma2(a0, wA.x, hd);
                fma2(a1, wA.y, hd);
                fma2(a2, wB.x, hd);
                fma2(a3, wB.y, hd);
            }
        }

        if (uok) {
            float2 gi = upk2(a0), gf = upk2(a1), gg = upk2(a2), go = upk2(a3);
            const bool m = (t < len);

            float i0 = 1.f / (1.f + __expf(-gi.x));
            float i1 = 1.f / (1.f + __expf(-gi.y));
            float f0 = 1.f / (1.f + __expf(-gf.x));
            float f1 = 1.f / (1.f + __expf(-gf.y));
            float g0 = tanhf(gg.x);
            float g1 = tanhf(gg.y);
            float o0 = 1.f / (1.f + __expf(-go.x));
            float o1 = 1.f / (1.f + __expf(-go.y));

            float cn0 = f0 * c0 + i0 * g0;
            float cn1 = f1 * c1 + i1 * g1;
            float hn0 = o0 * tanhf(cn0);
            float hn1 = o1 * tanhf(cn1);
            float ho0 = hp[u0];
            float ho1 = hp[u0 + 1];
            if (m) { c0 = cn0; c1 = cn1; }
            float hw0 = m ? hn0 : ho0;
            float hw1 = m ? hn1 : ho1;
            __stcg(&g_h[parity ^ 1][dir][bg][u0], hw0);
            __stcg(&g_h[parity ^ 1][dir][bg][u0 + 1], hw1);
            size_t oidx = ((size_t)bg * kT + t) * ostride + dir * kH + u0;
            outp[oidx]     = m ? hn0 : 0.f;
            outp[oidx + 1] = m ? hn1 : 0.f;

            // prefetch next step's gx (overlaps with sync wait)
            if (s + 1 < kT) {
                int tn = dir ? (kT - 2 - s) : (s + 1);
                const float* r = gx + ((size_t)bg * kT + tn) * 2000 + u0;
                v0 = *(const float2*)(r);
                v1 = *(const float2*)(r + kH);
                v2 = *(const float2*)(r + 2 * kH);
                v3 = *(const float2*)(r + 3 * kH);
            }
        }
        // publish this CTA's h for step s (tag+1)
        __threadfence();
        __syncthreads();
        if (tid == 0) stflag(&g_flag[gid][ub], tag + 1);
    }
}

// --------------------------- launcher --------------------------------------
extern "C" void kernel_launch(void* const* d_in, const int* in_sizes, int n_in,
                              void* d_out, int out_size) {
    const float* seqs  = (const float*)d_in[0];
    const void*  lens  = d_in[1];
    const float* Wih0f = (const float*)d_in[2];
    const float* Whh0f = (const float*)d_in[3];
    const float* b0f   = (const float*)d_in[4];
    const float* Wih0b = (const float*)d_in[5];
    const float* Whh0b = (const float*)d_in[6];
    const float* b0b   = (const float*)d_in[7];
    const float* Wih1f = (const float*)d_in[8];
    const float* Whh1f = (const float*)d_in[9];
    const float* b1f   = (const float*)d_in[10];
    const float* Wih1b = (const float*)d_in[11];
    const float* Whh1b = (const float*)d_in[12];
    const float* b1b   = (const float*)d_in[13];
    float* out = (float*)d_out;

    cudaFuncSetAttribute(k_rnn, cudaFuncAttributeMaxDynamicSharedMemorySize, kRnnSmem);

    k_len<<<1, 256>>>(lens);
    k_packW<<<16384, 256>>>(Whh0f, Whh0b, Whh1f, Whh1b);
    k_padWih<<<16000, 256>>>(Wih1f, Wih1b);
    k_zpad<<<3072, 256>>>();
    k_zero<<<512, 256>>>();

    dim3 gg(256, 16);
    // layer 0 (K=512)
    k_gemm<<<gg, 256>>>(seqs, 0, Wih0f, 0, b0f, 0, 512);
    k_gemm<<<gg, 256>>>(seqs, 0, Wih0b, 0, b0b, 1, 512);
    k_rnn<<<128, 256, kRnnSmem>>>(0, out);

    // layer 1 (K=1024, padded)
    k_zero<<<512, 256>>>();
    k_gemm<<<gg, 256>>>(nullptr, 1, nullptr, 1, b1f, 0, 1024);
    k_gemm<<<gg, 256>>>(nullptr, 1, nullptr, 2, b1b, 1, 1024);
    k_rnn<<<128, 256, kRnnSmem>>>(1, out);
}